// round 1
// baseline (speedup 1.0000x reference)
#include <cuda_runtime.h>
#include <cstddef>

// ---------------- problem constants (fixed by reference setup) ----------------
#define NGg    8
#define NVv    400
#define NCL    1200
#define KLIT   5
#define NNG    (2 * NVv + NCL)        // 2000 nodes per graph
#define NTOT   (NGg * NNG)            // 16000 nodes
#define D      128
#define LROWS  (NGg * 2 * NVv)        // 6400 literal rows (compact)
#define CROWS  (NGg * NCL)            // 9600 clause rows (compact)
#define NEDGE  (NGg * NCL * KLIT)     // 48000 edges
#define ROUNDS 26

// ---------------- device scratch (no allocation allowed) ----------------
__device__ float d_h[NTOT * D];
__device__ float d_c[NTOT * D];
__device__ float d_b1[CROWS * D];
__device__ float d_b2[CROWS * D];
__device__ float d_g[CROWS * 4 * D];
__device__ float d_vrow[LROWS];

// ---------------- GEMM: C[M,Nout] = A[M,128] * W[Nout,128(ldw)]^T ----------------
// A row-major with lda=128; optional row-gather via aidx.
// W row-major with row stride ldw (lets us slice lu_wih's [512,256] into two K=128 gemms).
// Epilogue: optional bias+relu, optional accumulate into C.
#define BM 64
#define BN 64
#define BK 16
#define SPAD 4

__global__ __launch_bounds__(256) void gemm_nt(
    const float* __restrict__ A, const int* __restrict__ aidx,
    const float* __restrict__ W, int ldw,
    const float* __restrict__ bias,
    float* __restrict__ C, int ldc,
    int relu, int acc)
{
    __shared__ float As[BK][BM + SPAD];
    __shared__ float Ws[BK][BN + SPAD];

    const int bm  = blockIdx.x * BM;
    const int bn  = blockIdx.y * BN;
    const int tid = threadIdx.x;
    const int tx  = tid & 15;          // 0..15  -> 4 output cols
    const int ty  = tid >> 4;          // 0..15  -> 4 output rows
    const int lr  = tid >> 2;          // 0..63 : tile row for loads
    const int lk  = (tid & 3) << 2;    // 0,4,8,12 : k offset for float4 load

    const int arow = bm + lr;
    const int ar   = aidx ? aidx[arow] : arow;
    const float* Aptr = A + (size_t)ar * D;
    const float* Wptr = W + (size_t)(bn + lr) * ldw;

    float accv[4][4] = {};

    for (int k0 = 0; k0 < D; k0 += BK) {
        float4 av = *(const float4*)(Aptr + k0 + lk);
        float4 wv = *(const float4*)(Wptr + k0 + lk);
        As[lk + 0][lr] = av.x; As[lk + 1][lr] = av.y;
        As[lk + 2][lr] = av.z; As[lk + 3][lr] = av.w;
        Ws[lk + 0][lr] = wv.x; Ws[lk + 1][lr] = wv.y;
        Ws[lk + 2][lr] = wv.z; Ws[lk + 3][lr] = wv.w;
        __syncthreads();

        #pragma unroll
        for (int kk = 0; kk < BK; kk++) {
            float4 a = *(const float4*)&As[kk][ty * 4];
            float4 w = *(const float4*)&Ws[kk][tx * 4];
            accv[0][0] += a.x * w.x; accv[0][1] += a.x * w.y;
            accv[0][2] += a.x * w.z; accv[0][3] += a.x * w.w;
            accv[1][0] += a.y * w.x; accv[1][1] += a.y * w.y;
            accv[1][2] += a.y * w.z; accv[1][3] += a.y * w.w;
            accv[2][0] += a.z * w.x; accv[2][1] += a.z * w.y;
            accv[2][2] += a.z * w.z; accv[2][3] += a.z * w.w;
            accv[3][0] += a.w * w.x; accv[3][1] += a.w * w.y;
            accv[3][2] += a.w * w.z; accv[3][3] += a.w * w.w;
        }
        __syncthreads();
    }

    const int row = bm + ty * 4;
    const int col = bn + tx * 4;
    float4 bv = make_float4(0.f, 0.f, 0.f, 0.f);
    if (bias) bv = *(const float4*)(bias + col);

    #pragma unroll
    for (int i = 0; i < 4; i++) {
        float4 v = make_float4(accv[i][0], accv[i][1], accv[i][2], accv[i][3]);
        v.x += bv.x; v.y += bv.y; v.z += bv.z; v.w += bv.w;
        if (relu) {
            v.x = fmaxf(v.x, 0.f); v.y = fmaxf(v.y, 0.f);
            v.z = fmaxf(v.z, 0.f); v.w = fmaxf(v.w, 0.f);
        }
        float* cp = C + (size_t)(row + i) * ldc + col;
        if (acc) {
            float4 o = *(float4*)cp;
            v.x += o.x; v.y += o.y; v.z += o.z; v.w += o.w;
        }
        *(float4*)cp = v;
    }
}

// ---------------- init h, c ----------------
__global__ void init_hc(const float* __restrict__ Lw, const float* __restrict__ Lb,
                        const float* __restrict__ Cw, const float* __restrict__ Cb,
                        float* __restrict__ h, float* __restrict__ c)
{
    int n = blockIdx.x;
    int d = threadIdx.x;
    int loc = n % NNG;
    float v = (loc < 2 * NVv) ? (Lw[d] + Lb[d]) : (Cw[d] + Cb[d]);
    h[(size_t)n * D + d] = v;
    c[(size_t)n * D + d] = 0.f;
}

// ---------------- clause aggregation (pure gather: edges for clause cr are [cr*5, cr*5+5)) -----
__global__ void clause_agg(const float* __restrict__ m_l, const int* __restrict__ edge_src,
                           float* __restrict__ agg)
{
    int cr = blockIdx.x;     // compact clause row 0..CROWS-1
    int d  = threadIdx.x;    // 0..127
    const int* es = edge_src + cr * KLIT;
    float s = 0.f;
    #pragma unroll
    for (int k = 0; k < KLIT; k++) {
        int gsrc = es[k];                              // global literal node id
        int csrc = (gsrc / NNG) * (2 * NVv) + (gsrc % NNG); // compact literal row
        s += m_l[(size_t)csrc * D + d];
    }
    agg[(size_t)cr * D + d] = s;
}

// ---------------- literal aggregation (atomic scatter over 48000 edges) ----------------
__global__ void lit_scatter(const float* __restrict__ m_c, const int* __restrict__ edge_src,
                            float* __restrict__ agg)
{
    int e = blockIdx.x;      // edge id
    int d = threadIdx.x;
    int cdst = e / KLIT;     // compact clause row of this edge (edges laid out (g,c,k))
    int gsrc = edge_src[e];
    int csrc = (gsrc / NNG) * (2 * NVv) + (gsrc % NNG);
    atomicAdd(&agg[(size_t)csrc * D + d], m_c[(size_t)cdst * D + d]);
}

__global__ void zero_buf(float* __restrict__ p, int n)
{
    int i = blockIdx.x * blockDim.x + threadIdx.x;
    if (i < n) p[i] = 0.f;
}

// ---------------- pointwise LSTM update ----------------
__device__ __forceinline__ float sigm(float x) { return 1.f / (1.f + expf(-x)); }

__global__ void lstm_update(const float* __restrict__ g,
                            const float* __restrict__ bih, const float* __restrict__ bhh,
                            const int* __restrict__ nodeidx,
                            float* __restrict__ h, float* __restrict__ c)
{
    int r = blockIdx.x;
    int d = threadIdx.x;
    const float* gr = g + (size_t)r * (4 * D);
    float gi = gr[0 * D + d] + bih[0 * D + d] + bhh[0 * D + d];
    float gf = gr[1 * D + d] + bih[1 * D + d] + bhh[1 * D + d];
    float gg = gr[2 * D + d] + bih[2 * D + d] + bhh[2 * D + d];
    float go = gr[3 * D + d] + bih[3 * D + d] + bhh[3 * D + d];
    int node = nodeidx[r];
    size_t off = (size_t)node * D + d;
    float c2 = sigm(gf) * c[off] + sigm(gi) * tanhf(gg);
    c[off] = c2;
    h[off] = sigm(go) * tanhf(c2);
}

// ---------------- vote head ----------------
__global__ void vote_row(const float* __restrict__ v2, const float* __restrict__ w2,
                         const float* __restrict__ b2, float* __restrict__ vrow)
{
    int r = blockIdx.x;
    int t = threadIdx.x;      // 128 threads
    float p = v2[(size_t)r * D + t] * w2[t];
    #pragma unroll
    for (int s = 16; s > 0; s >>= 1) p += __shfl_down_sync(0xffffffff, p, s);
    __shared__ float ws[4];
    if ((t & 31) == 0) ws[t >> 5] = p;
    __syncthreads();
    if (t == 0) vrow[r] = ws[0] + ws[1] + ws[2] + ws[3] + b2[0];
}

__global__ void graph_mean(const float* __restrict__ vrow, const int* __restrict__ n_vars,
                           float* __restrict__ out)
{
    int g = blockIdx.x;       // 8 graphs
    int t = threadIdx.x;      // 256 threads
    float s = 0.f;
    for (int i = t; i < 2 * NVv; i += 256) s += vrow[g * (2 * NVv) + i];
    __shared__ float red[256];
    red[t] = s;
    __syncthreads();
    for (int st = 128; st > 0; st >>= 1) {
        if (t < st) red[t] += red[t + st];
        __syncthreads();
    }
    if (t == 0) out[g] = red[0] / (2.f * (float)n_vars[g]);
}

// ---------------- host orchestration ----------------
static inline void gemm_go(const float* A, const int* aidx, const float* W, int ldw,
                           const float* bias, float* C, int M, int Nout, int relu, int acc)
{
    dim3 grid(M / BM, Nout / BN);
    gemm_nt<<<grid, 256>>>(A, aidx, W, ldw, bias, C, Nout, relu, acc);
}

extern "C" void kernel_launch(void* const* d_in, const int* in_sizes, int n_in,
                              void* d_out, int out_size)
{
    const int* edge_src   = (const int*)d_in[0];
    // d_in[1] = edge_dst (redundant: clause of edge e is e/KLIT)
    const int* l_index    = (const int*)d_in[2];
    const int* c_index    = (const int*)d_in[3];
    const int* flip_index = (const int*)d_in[4];
    // d_in[5] = batch (structure is regular; not needed)
    const int* n_vars     = (const int*)d_in[6];
    const float* L_init_w = (const float*)d_in[7];
    const float* L_init_b = (const float*)d_in[8];
    const float* C_init_w = (const float*)d_in[9];
    const float* C_init_b = (const float*)d_in[10];
    const float* lmsg_w   = (const float*)d_in[11];
    const float* lmsg_b   = (const float*)d_in[12];
    const float* cmsg_w   = (const float*)d_in[13];
    const float* cmsg_b   = (const float*)d_in[14];
    const float* lu_wih   = (const float*)d_in[15];  // [512,256]
    const float* lu_whh   = (const float*)d_in[16];  // [512,128]
    const float* lu_bih   = (const float*)d_in[17];
    const float* lu_bhh   = (const float*)d_in[18];
    const float* cu_wih   = (const float*)d_in[19];  // [512,128]
    const float* cu_whh   = (const float*)d_in[20];  // [512,128]
    const float* cu_bih   = (const float*)d_in[21];
    const float* cu_bhh   = (const float*)d_in[22];
    const float* vote_w0  = (const float*)d_in[23];
    const float* vote_b0  = (const float*)d_in[24];
    const float* vote_w1  = (const float*)d_in[25];
    const float* vote_b1  = (const float*)d_in[26];
    const float* vote_w2  = (const float*)d_in[27];  // [1,128]
    const float* vote_b2  = (const float*)d_in[28];  // [1]

    float *h, *c, *b1, *b2, *g, *vrow;
    cudaGetSymbolAddress((void**)&h,    d_h);
    cudaGetSymbolAddress((void**)&c,    d_c);
    cudaGetSymbolAddress((void**)&b1,   d_b1);
    cudaGetSymbolAddress((void**)&b2,   d_b2);
    cudaGetSymbolAddress((void**)&g,    d_g);
    cudaGetSymbolAddress((void**)&vrow, d_vrow);

    init_hc<<<NTOT, D>>>(L_init_w, L_init_b, C_init_w, C_init_b, h, c);

    for (int r = 0; r < ROUNDS; r++) {
        // literal message MLP (only literal rows are ever consumed)
        gemm_go(h,  l_index, lmsg_w + 0 * D * D, D, lmsg_b + 0 * D, b1, LROWS, D, 1, 0);
        gemm_go(b1, nullptr, lmsg_w + 1 * D * D, D, lmsg_b + 1 * D, b2, LROWS, D, 1, 0);
        gemm_go(b2, nullptr, lmsg_w + 2 * D * D, D, lmsg_b + 2 * D, b1, LROWS, D, 0, 0);
        // clause aggregation: gather 5 literal messages per clause
        clause_agg<<<CROWS, D>>>(b1, edge_src, b2);
        // clause LSTM gates: g = agg @ cu_wih^T + h[c] @ cu_whh^T
        gemm_go(b2, nullptr, cu_wih, D, nullptr, g, CROWS, 4 * D, 0, 0);
        gemm_go(h,  c_index, cu_whh, D, nullptr, g, CROWS, 4 * D, 0, 1);
        lstm_update<<<CROWS, D>>>(g, cu_bih, cu_bhh, c_index, h, c);
        // clause message MLP (on updated clause h)
        gemm_go(h,  c_index, cmsg_w + 0 * D * D, D, cmsg_b + 0 * D, b1, CROWS, D, 1, 0);
        gemm_go(b1, nullptr, cmsg_w + 1 * D * D, D, cmsg_b + 1 * D, b2, CROWS, D, 1, 0);
        gemm_go(b2, nullptr, cmsg_w + 2 * D * D, D, cmsg_b + 2 * D, b1, CROWS, D, 0, 0);
        // literal aggregation: scatter clause messages to literals
        zero_buf<<<(LROWS * D + 255) / 256, 256>>>(b2, LROWS * D);
        lit_scatter<<<NEDGE, D>>>(b1, edge_src, b2);
        // literal LSTM gates: g = agg @ Wih[:, :128]^T + h[flip] @ Wih[:, 128:]^T + h[l] @ Whh^T
        gemm_go(b2, nullptr, lu_wih,     2 * D, nullptr, g, LROWS, 4 * D, 0, 0);
        gemm_go(h,  flip_index, lu_wih + D, 2 * D, nullptr, g, LROWS, 4 * D, 0, 1);
        gemm_go(h,  l_index, lu_whh,     D,     nullptr, g, LROWS, 4 * D, 0, 1);
        lstm_update<<<LROWS, D>>>(g, lu_bih, lu_bhh, l_index, h, c);
    }

    // vote head
    gemm_go(h,  l_index, vote_w0, D, vote_b0, b1, LROWS, D, 1, 0);
    gemm_go(b1, nullptr, vote_w1, D, vote_b1, b2, LROWS, D, 1, 0);
    vote_row<<<LROWS, D>>>(b2, vote_w2, vote_b2, vrow);
    graph_mean<<<NGg, 256>>>(vrow, n_vars, (float*)d_out);

    (void)in_sizes; (void)n_in; (void)out_size;
}

// round 2
// speedup vs baseline: 1.9059x; 1.9059x over previous
#include <cuda_runtime.h>
#include <cstddef>

// ---------------- problem constants ----------------
#define NGg    8
#define NVv    400
#define NCL    1200
#define KLIT   5
#define NNG    (2 * NVv + NCL)        // 2000 nodes/graph
#define NTOT   (NGg * NNG)            // 16000 nodes
#define D      128
#define LROWS  (NGg * 2 * NVv)        // 6400 literal rows
#define CROWS  (NGg * NCL)            // 9600 clause rows
#define EPG    (NCL * KLIT)           // 6000 edges per graph
#define ROUNDS 26
#define ADJW   40

// ---------------- device scratch ----------------
__device__ float d_h[NTOT * D];
__device__ float d_c[NTOT * D];
__device__ float d_b1[CROWS * D];
__device__ float d_b2[CROWS * D];
__device__ float d_b3[CROWS * D];
__device__ int   d_adj[LROWS * ADJW];
__device__ int   d_deg[LROWS];
__device__ float d_vrow[LROWS];

// ---------------- helpers ----------------
__device__ __forceinline__ unsigned f2tf(float x) {
    unsigned r; asm("cvt.rna.tf32.f32 %0, %1;" : "=r"(r) : "f"(x)); return r;
}
__device__ __forceinline__ void mma_tf32(float c[4],
    unsigned a0, unsigned a1, unsigned a2, unsigned a3, unsigned b0, unsigned b1)
{
    asm volatile(
        "mma.sync.aligned.m16n8k8.row.col.f32.tf32.tf32.f32 "
        "{%0,%1,%2,%3}, {%4,%5,%6,%7}, {%8,%9}, {%0,%1,%2,%3};"
        : "+f"(c[0]), "+f"(c[1]), "+f"(c[2]), "+f"(c[3])
        : "r"(a0), "r"(a1), "r"(a2), "r"(a3), "r"(b0), "r"(b1));
}
__device__ __forceinline__ float sigm(float x) { return 1.f / (1.f + expf(-x)); }

// ---------------- init h, c ----------------
__global__ void init_hc(const float* __restrict__ Lw, const float* __restrict__ Lb,
                        const float* __restrict__ Cw, const float* __restrict__ Cb,
                        float* __restrict__ h, float* __restrict__ c)
{
    int n = blockIdx.x, d = threadIdx.x;
    int loc = n % NNG;
    float v = (loc < 2 * NVv) ? (Lw[d] + Lb[d]) : (Cw[d] + Cb[d]);
    h[(size_t)n * D + d] = v;
    c[(size_t)n * D + d] = 0.f;
}

// ---------------- one-time reverse adjacency (ELL) build: deterministic ----------------
__global__ void build_adj(const int* __restrict__ edge_src,
                          int* __restrict__ adj, int* __restrict__ deg)
{
    int lit = blockIdx.x * 160 + threadIdx.x;   // compact literal row (blocks align to graphs)
    int g = lit / (2 * NVv);
    int loc = lit % (2 * NVv);
    int mynode = g * NNG + loc;
    const int* es = edge_src + g * EPG;
    int cnt = 0;
    for (int j = 0; j < EPG; j++) {
        if (es[j] == mynode) {
            if (cnt < ADJW) adj[lit * ADJW + cnt] = g * NCL + j / KLIT;
            cnt++;
        }
    }
    deg[lit] = cnt < ADJW ? cnt : ADJW;
}

// ---------------- fused MLP (NL layers of DxD), tf32 mma, BM=32, 128 threads ----------
template<int NL>
__global__ __launch_bounds__(128) void mlp_fused(
    const float* __restrict__ h, const int* __restrict__ gidx,
    const float* __restrict__ W0, const float* __restrict__ B0,
    const float* __restrict__ W1, const float* __restrict__ B1,
    const float* __restrict__ W2, const float* __restrict__ B2,
    float* __restrict__ out, int relu_last)
{
    __shared__ unsigned X[32][132];     // tf32 bits of current activation
    __shared__ unsigned Wsm[128][36];   // tf32 bits of W k-chunk

    const int tid  = threadIdx.x;
    const int lane = tid & 31;
    const int warp = tid >> 5;          // 0..3 -> 32-col slice
    const int grp  = lane >> 2;
    const int tig  = lane & 3;
    const int bm   = blockIdx.x * 32;

    // initial gather: X = tf32(h[gidx[row]])
    #pragma unroll
    for (int t = 0; t < 8; t++) {
        int flat = tid + 128 * t;           // float4 id: 32 rows x 32 f4
        int r = flat >> 5, kb = flat & 31;
        float4 v = *(const float4*)(h + (size_t)gidx[bm + r] * D + kb * 4);
        X[r][kb * 4 + 0] = f2tf(v.x); X[r][kb * 4 + 1] = f2tf(v.y);
        X[r][kb * 4 + 2] = f2tf(v.z); X[r][kb * 4 + 3] = f2tf(v.w);
    }

    const float* Wl[3] = { W0, W1, W2 };
    const float* Bl[3] = { B0, B1, B2 };

    for (int l = 0; l < NL; l++) {
        float acc[2][4][4];
        #pragma unroll
        for (int mi = 0; mi < 2; mi++)
            #pragma unroll
            for (int ni = 0; ni < 4; ni++)
                #pragma unroll
                for (int u = 0; u < 4; u++) acc[mi][ni][u] = 0.f;

        const float* W = Wl[l];
        for (int ch = 0; ch < 4; ch++) {
            __syncthreads();
            #pragma unroll
            for (int t = 0; t < 8; t++) {
                int flat = tid + 128 * t;       // 128 n x 8 f4
                int n = flat >> 3, kb = flat & 7;
                float4 v = *(const float4*)(W + (size_t)n * D + ch * 32 + kb * 4);
                Wsm[n][kb * 4 + 0] = f2tf(v.x); Wsm[n][kb * 4 + 1] = f2tf(v.y);
                Wsm[n][kb * 4 + 2] = f2tf(v.z); Wsm[n][kb * 4 + 3] = f2tf(v.w);
            }
            __syncthreads();
            #pragma unroll
            for (int ks = 0; ks < 4; ks++) {
                int kk = ch * 32 + ks * 8;
                unsigned a[2][4], b[4][2];
                #pragma unroll
                for (int mi = 0; mi < 2; mi++) {
                    int r = mi * 16 + grp;
                    a[mi][0] = X[r    ][kk + tig];
                    a[mi][1] = X[r + 8][kk + tig];
                    a[mi][2] = X[r    ][kk + tig + 4];
                    a[mi][3] = X[r + 8][kk + tig + 4];
                }
                #pragma unroll
                for (int ni = 0; ni < 4; ni++) {
                    int n = warp * 32 + ni * 8 + grp;
                    b[ni][0] = Wsm[n][ks * 8 + tig];
                    b[ni][1] = Wsm[n][ks * 8 + tig + 4];
                }
                #pragma unroll
                for (int mi = 0; mi < 2; mi++)
                    #pragma unroll
                    for (int ni = 0; ni < 4; ni++)
                        mma_tf32(acc[mi][ni], a[mi][0], a[mi][1], a[mi][2], a[mi][3],
                                 b[ni][0], b[ni][1]);
            }
        }
        __syncthreads();
        const float* B = Bl[l];
        int do_relu = (l < NL - 1) || relu_last;
        #pragma unroll
        for (int mi = 0; mi < 2; mi++) {
            #pragma unroll
            for (int ni = 0; ni < 4; ni++) {
                int r0 = mi * 16 + grp;
                int c0 = warp * 32 + ni * 8 + 2 * tig;
                #pragma unroll
                for (int u = 0; u < 4; u++) {
                    int r = r0 + (u >> 1) * 8;
                    int cc = c0 + (u & 1);
                    float v = acc[mi][ni][u] + B[cc];
                    if (do_relu) v = fmaxf(v, 0.f);
                    if (l == NL - 1) out[(size_t)(bm + r) * D + cc] = v;
                    else             X[r][cc] = f2tf(v);
                }
            }
        }
    }
}

// ---------------- clause aggregation: gather 5 contiguous edges ----------------
__global__ void clause_agg(const float* __restrict__ m_l, const int* __restrict__ edge_src,
                           float* __restrict__ agg)
{
    int cr = blockIdx.x, d = threadIdx.x;
    const int* es = edge_src + cr * KLIT;
    float s = 0.f;
    #pragma unroll
    for (int k = 0; k < KLIT; k++) {
        int gsrc = es[k];
        int csrc = (gsrc / NNG) * (2 * NVv) + (gsrc % NNG);
        s += m_l[(size_t)csrc * D + d];
    }
    agg[(size_t)cr * D + d] = s;
}

// ---------------- literal aggregation: ELL gather ----------------
__global__ void lit_agg(const float* __restrict__ msg, const int* __restrict__ adj,
                        const int* __restrict__ deg, float* __restrict__ agg)
{
    int r = blockIdx.x, d = threadIdx.x;
    int n = deg[r];
    float s = 0.f;
    for (int t = 0; t < n; t++) s += msg[(size_t)adj[r * ADJW + t] * D + d];
    agg[(size_t)r * D + d] = s;
}

// ---------------- staging gathers (snapshot old h to avoid RAW races) -------------
__global__ void gather2(const float* __restrict__ h, const int* __restrict__ i1,
                        const int* __restrict__ i2, float* __restrict__ o1,
                        float* __restrict__ o2)
{
    int r = blockIdx.x, d = threadIdx.x;
    o1[(size_t)r * D + d] = h[(size_t)i1[r] * D + d];
    o2[(size_t)r * D + d] = h[(size_t)i2[r] * D + d];
}
__global__ void gather1(const float* __restrict__ h, const int* __restrict__ i1,
                        float* __restrict__ o1)
{
    int r = blockIdx.x, d = threadIdx.x;
    o1[(size_t)r * D + d] = h[(size_t)i1[r] * D + d];
}

// ---------------- fused gate GEMM (K-concat) + LSTM epilogue -----------------
// A columns: [0,128)=agg, [128,KTOT-128)=x2, [KTOT-128,KTOT)=x3  (all compact-row, ld=D)
// W rows n in this block: n = g*128 + dd0 + dd; W cols: [0,KTOT-128)=Wih(ldwih), rest Whh(ld D)
// BM=64, 128 gate-cols per block (4 gates x 32 dd), 256 threads, grid (M/64, 4)
template<int KTOT>
__global__ __launch_bounds__(256) void gate_lstm(
    const float* __restrict__ agg, const float* __restrict__ x2,
    const float* __restrict__ x3,
    const int* __restrict__ nodeidx,
    const float* __restrict__ Wih, int ldwih,
    const float* __restrict__ Whh,
    const float* __restrict__ bih, const float* __restrict__ bhh,
    float* __restrict__ hg, float* __restrict__ cg)
{
    __shared__ __align__(16) unsigned char smem[64 * 132 * 4]; // gbuf is biggest
    unsigned (*As)[36]  = (unsigned(*)[36])smem;
    unsigned (*Wsm)[36] = (unsigned(*)[36])(smem + 64 * 36 * 4);
    float    (*gbuf)[132] = (float(*)[132])smem;

    const int tid  = threadIdx.x;
    const int lane = tid & 31;
    const int warp = tid >> 5;
    const int wr   = warp & 1;       // 2 row-warps
    const int wc   = warp >> 1;      // 4 col-warps (gate wc)
    const int grp  = lane >> 2;
    const int tig  = lane & 3;
    const int bm   = blockIdx.x * 64;
    const int dd0  = blockIdx.y * 32;

    float acc[2][4][4];
    #pragma unroll
    for (int mi = 0; mi < 2; mi++)
        #pragma unroll
        for (int ni = 0; ni < 4; ni++)
            #pragma unroll
            for (int u = 0; u < 4; u++) acc[mi][ni][u] = 0.f;

    const int NCH = KTOT / 32;
    for (int ch = 0; ch < NCH; ch++) {
        int k0 = ch * 32;
        __syncthreads();
        // A tile: 64 x 32
        #pragma unroll
        for (int t = 0; t < 2; t++) {
            int flat = tid + 256 * t;      // 512 float4
            int lr = flat >> 3, kb = flat & 7;
            int k = k0 + kb * 4;
            const float* src;
            if (k0 < 128)                 src = agg + (size_t)(bm + lr) * D + k;
            else if (k0 < KTOT - 128)     src = x2  + (size_t)(bm + lr) * D + (k - 128);
            else                          src = x3  + (size_t)(bm + lr) * D + (k - (KTOT - 128));
            float4 v = *(const float4*)src;
            As[lr][kb * 4 + 0] = f2tf(v.x); As[lr][kb * 4 + 1] = f2tf(v.y);
            As[lr][kb * 4 + 2] = f2tf(v.z); As[lr][kb * 4 + 3] = f2tf(v.w);
        }
        // W tile: 128 x 32 (row wrow -> n = (wrow>>5)*128 + dd0 + (wrow&31))
        #pragma unroll
        for (int t = 0; t < 4; t++) {
            int flat = tid + 256 * t;      // 1024 float4
            int wrow = flat >> 3, kb = flat & 7;
            int k = k0 + kb * 4;
            int n = (wrow >> 5) * 128 + dd0 + (wrow & 31);
            const float* src = (k0 < KTOT - 128)
                ? Wih + (size_t)n * ldwih + k
                : Whh + (size_t)n * D + (k - (KTOT - 128));
            float4 v = *(const float4*)src;
            Wsm[wrow][kb * 4 + 0] = f2tf(v.x); Wsm[wrow][kb * 4 + 1] = f2tf(v.y);
            Wsm[wrow][kb * 4 + 2] = f2tf(v.z); Wsm[wrow][kb * 4 + 3] = f2tf(v.w);
        }
        __syncthreads();
        #pragma unroll
        for (int ks = 0; ks < 4; ks++) {
            unsigned a[2][4], b[4][2];
            #pragma unroll
            for (int mi = 0; mi < 2; mi++) {
                int r = wr * 32 + mi * 16 + grp;
                a[mi][0] = As[r    ][ks * 8 + tig];
                a[mi][1] = As[r + 8][ks * 8 + tig];
                a[mi][2] = As[r    ][ks * 8 + tig + 4];
                a[mi][3] = As[r + 8][ks * 8 + tig + 4];
            }
            #pragma unroll
            for (int ni = 0; ni < 4; ni++) {
                int n = wc * 32 + ni * 8 + grp;
                b[ni][0] = Wsm[n][ks * 8 + tig];
                b[ni][1] = Wsm[n][ks * 8 + tig + 4];
            }
            #pragma unroll
            for (int mi = 0; mi < 2; mi++)
                #pragma unroll
                for (int ni = 0; ni < 4; ni++)
                    mma_tf32(acc[mi][ni], a[mi][0], a[mi][1], a[mi][2], a[mi][3],
                             b[ni][0], b[ni][1]);
        }
    }

    // stage gates to smem (overlaps As/Ws; sync first)
    __syncthreads();
    #pragma unroll
    for (int mi = 0; mi < 2; mi++) {
        #pragma unroll
        for (int ni = 0; ni < 4; ni++) {
            int r0 = wr * 32 + mi * 16 + grp;
            int c0 = wc * 32 + ni * 8 + 2 * tig;
            gbuf[r0    ][c0    ] = acc[mi][ni][0];
            gbuf[r0    ][c0 + 1] = acc[mi][ni][1];
            gbuf[r0 + 8][c0    ] = acc[mi][ni][2];
            gbuf[r0 + 8][c0 + 1] = acc[mi][ni][3];
        }
    }
    __syncthreads();

    // pointwise LSTM: thread -> (dd, base row), 8 row-iterations
    int ddl = tid & 31;
    int rl0 = tid >> 5;
    int dd  = dd0 + ddl;
    float bi0 = bih[0 * 128 + dd] + bhh[0 * 128 + dd];
    float bi1 = bih[1 * 128 + dd] + bhh[1 * 128 + dd];
    float bi2 = bih[2 * 128 + dd] + bhh[2 * 128 + dd];
    float bi3 = bih[3 * 128 + dd] + bhh[3 * 128 + dd];
    #pragma unroll
    for (int it = 0; it < 8; it++) {
        int row = it * 8 + rl0;
        int node = nodeidx[bm + row];
        float gi = gbuf[row][0 * 32 + ddl] + bi0;
        float gf = gbuf[row][1 * 32 + ddl] + bi1;
        float gg = gbuf[row][2 * 32 + ddl] + bi2;
        float go = gbuf[row][3 * 32 + ddl] + bi3;
        size_t off = (size_t)node * D + dd;
        float c2 = sigm(gf) * cg[off] + sigm(gi) * tanhf(gg);
        cg[off] = c2;
        hg[off] = sigm(go) * tanhf(c2);
    }
}

// ---------------- vote head ----------------
__global__ void vote_row(const float* __restrict__ v2, const float* __restrict__ w2,
                         const float* __restrict__ b2, float* __restrict__ vrow)
{
    int r = blockIdx.x, t = threadIdx.x;
    float p = v2[(size_t)r * D + t] * w2[t];
    #pragma unroll
    for (int s = 16; s > 0; s >>= 1) p += __shfl_down_sync(0xffffffff, p, s);
    __shared__ float ws[4];
    if ((t & 31) == 0) ws[t >> 5] = p;
    __syncthreads();
    if (t == 0) vrow[r] = ws[0] + ws[1] + ws[2] + ws[3] + b2[0];
}

__global__ void graph_mean(const float* __restrict__ vrow, const int* __restrict__ n_vars,
                           float* __restrict__ out)
{
    int g = blockIdx.x, t = threadIdx.x;
    float s = 0.f;
    for (int i = t; i < 2 * NVv; i += 256) s += vrow[g * (2 * NVv) + i];
    __shared__ float red[256];
    red[t] = s;
    __syncthreads();
    for (int st = 128; st > 0; st >>= 1) {
        if (t < st) red[t] += red[t + st];
        __syncthreads();
    }
    if (t == 0) out[g] = red[0] / (2.f * (float)n_vars[g]);
}

// ---------------- host orchestration ----------------
extern "C" void kernel_launch(void* const* d_in, const int* in_sizes, int n_in,
                              void* d_out, int out_size)
{
    const int* edge_src   = (const int*)d_in[0];
    const int* l_index    = (const int*)d_in[2];
    const int* c_index    = (const int*)d_in[3];
    const int* flip_index = (const int*)d_in[4];
    const int* n_vars     = (const int*)d_in[6];
    const float* L_init_w = (const float*)d_in[7];
    const float* L_init_b = (const float*)d_in[8];
    const float* C_init_w = (const float*)d_in[9];
    const float* C_init_b = (const float*)d_in[10];
    const float* lmsg_w   = (const float*)d_in[11];
    const float* lmsg_b   = (const float*)d_in[12];
    const float* cmsg_w   = (const float*)d_in[13];
    const float* cmsg_b   = (const float*)d_in[14];
    const float* lu_wih   = (const float*)d_in[15];  // [512,256]
    const float* lu_whh   = (const float*)d_in[16];  // [512,128]
    const float* lu_bih   = (const float*)d_in[17];
    const float* lu_bhh   = (const float*)d_in[18];
    const float* cu_wih   = (const float*)d_in[19];  // [512,128]
    const float* cu_whh   = (const float*)d_in[20];  // [512,128]
    const float* cu_bih   = (const float*)d_in[21];
    const float* cu_bhh   = (const float*)d_in[22];
    const float* vote_w0  = (const float*)d_in[23];
    const float* vote_b0  = (const float*)d_in[24];
    const float* vote_w1  = (const float*)d_in[25];
    const float* vote_b1  = (const float*)d_in[26];
    const float* vote_w2  = (const float*)d_in[27];
    const float* vote_b2  = (const float*)d_in[28];

    float *h, *c, *b1, *b2, *b3, *vrow;
    int *adj, *deg;
    cudaGetSymbolAddress((void**)&h,    d_h);
    cudaGetSymbolAddress((void**)&c,    d_c);
    cudaGetSymbolAddress((void**)&b1,   d_b1);
    cudaGetSymbolAddress((void**)&b2,   d_b2);
    cudaGetSymbolAddress((void**)&b3,   d_b3);
    cudaGetSymbolAddress((void**)&adj,  d_adj);
    cudaGetSymbolAddress((void**)&deg,  d_deg);
    cudaGetSymbolAddress((void**)&vrow, d_vrow);

    init_hc<<<NTOT, D>>>(L_init_w, L_init_b, C_init_w, C_init_b, h, c);
    build_adj<<<LROWS / 160, 160>>>(edge_src, adj, deg);

    for (int r = 0; r < ROUNDS; r++) {
        // literal message MLP (3 layers) -> b1[0:LROWS]
        mlp_fused<3><<<LROWS / 32, 128>>>(h, l_index,
            lmsg_w + 0 * D * D, lmsg_b + 0 * D,
            lmsg_w + 1 * D * D, lmsg_b + 1 * D,
            lmsg_w + 2 * D * D, lmsg_b + 2 * D, b1, 0);
        // clause aggregation -> b2
        clause_agg<<<CROWS, D>>>(b1, edge_src, b2);
        // snapshot old clause h -> b1 (b1 free after clause_agg)
        gather1<<<CROWS, D>>>(h, c_index, b1);
        // clause gates (K=256: [agg | h_c]) + LSTM epilogue
        gate_lstm<256><<<dim3(CROWS / 64, 4), 256>>>(b2, b2, b1, c_index,
            cu_wih, D, cu_whh, cu_bih, cu_bhh, h, c);
        // clause message MLP -> b1[0:CROWS]
        mlp_fused<3><<<CROWS / 32, 128>>>(h, c_index,
            cmsg_w + 0 * D * D, cmsg_b + 0 * D,
            cmsg_w + 1 * D * D, cmsg_b + 1 * D,
            cmsg_w + 2 * D * D, cmsg_b + 2 * D, b1, 0);
        // literal aggregation (ELL gather) -> b2
        lit_agg<<<LROWS, D>>>(b1, adj, deg, b2);
        // snapshot old h[flip] -> b1, old h[lit] -> b3
        gather2<<<LROWS, D>>>(h, flip_index, l_index, b1, b3);
        // literal gates (K=384: [agg | h_flip | h_lit]) + LSTM epilogue
        gate_lstm<384><<<dim3(LROWS / 64, 4), 256>>>(b2, b1, b3, l_index,
            lu_wih, 2 * D, lu_whh, lu_bih, lu_bhh, h, c);
    }

    // vote head: 2 relu layers, then dot + per-graph mean
    mlp_fused<2><<<LROWS / 32, 128>>>(h, l_index,
        vote_w0, vote_b0, vote_w1, vote_b1, vote_w1, vote_b1, b1, 1);
    vote_row<<<LROWS, D>>>(b1, vote_w2, vote_b2, vrow);
    graph_mean<<<NGg, 256>>>(vrow, n_vars, (float*)d_out);

    (void)in_sizes; (void)n_in; (void)out_size;
}